// round 10
// baseline (speedup 1.0000x reference)
#include <cuda_runtime.h>
#include <cuda_bf16.h>
#include <math.h>
#include <stdint.h>

#define D      128
#define NMAX   200000
#define EMAX   600000
#define GMAX   10000
#define EROWS  128
#define SA     136          // smem tile stride in bf16 elements

// ---------------- scratch (device globals; no runtime allocation) -----------
__device__ float S_Ah [(size_t)NMAX * D];   // A(h), later G(h_new)
__device__ float S_Dh [(size_t)NMAX * D];   // D(h) -> h_pre in place
__device__ float S_Eh [(size_t)NMAX * D];   // E(h)
__device__ float S_num[(size_t)NMAX * D];
__device__ float S_den[(size_t)NMAX * D];
__device__ float S_E1 [(size_t)EMAX * D];   // e_pre, later H(e_new)
__device__ float S_Cu [(size_t)GMAX * D];
__device__ float S_Fu [(size_t)GMAX * D];
__device__ float S_Iu [(size_t)GMAX * D];
__device__ float S_accG [(size_t)GMAX * D];
__device__ float S_accHe[(size_t)GMAX * D];
__device__ float S_cnt[GMAX];
__device__ float S_stats[8 * D];
// transposed bf16 split weights: [9][n=128][k=128]
__device__ __align__(16) __nv_bfloat16 S_Wh[9 * D * D];
__device__ __align__(16) __nv_bfloat16 S_Wl[9 * D * D];

// ---------------- helpers ----------------------------------------------------
__device__ __forceinline__ uint32_t smem_u32(const void* p) {
    uint32_t a;
    asm("{ .reg .u64 t; cvta.to.shared.u64 t, %1; cvt.u32.u64 %0, t; }"
        : "=r"(a) : "l"(p));
    return a;
}
__device__ __forceinline__ void ldm_x4(uint32_t& r0, uint32_t& r1,
                                       uint32_t& r2, uint32_t& r3, uint32_t a) {
    asm volatile("ldmatrix.sync.aligned.m8n8.x4.shared.b16 {%0,%1,%2,%3}, [%4];"
                 : "=r"(r0), "=r"(r1), "=r"(r2), "=r"(r3) : "r"(a));
}
__device__ __forceinline__ void mma16816(float* c, const uint32_t* a,
                                         const uint32_t* b) {
    asm volatile(
        "mma.sync.aligned.m16n8k16.row.col.f32.bf16.bf16.f32 "
        "{%0,%1,%2,%3}, {%4,%5,%6,%7}, {%8,%9}, {%0,%1,%2,%3};"
        : "+f"(c[0]), "+f"(c[1]), "+f"(c[2]), "+f"(c[3])
        : "r"(a[0]), "r"(a[1]), "r"(a[2]), "r"(a[3]), "r"(b[0]), "r"(b[1]));
}
__device__ __forceinline__ void red_add_v4(float* p, float4 v) {
    asm volatile("red.global.add.v4.f32 [%0], {%1,%2,%3,%4};"
                 :: "l"(p), "f"(v.x), "f"(v.y), "f"(v.z), "f"(v.w) : "memory");
}
__device__ __forceinline__ void cpa16(uint32_t dst, const void* src) {
    asm volatile("cp.async.cg.shared.global [%0], [%1], 16;"
                 :: "r"(dst), "l"(src) : "memory");
}
__device__ __forceinline__ void cpa_commit() {
    asm volatile("cp.async.commit_group;" ::: "memory");
}
__device__ __forceinline__ void cpa_wait0() {
    asm volatile("cp.async.wait_group 0;" ::: "memory");
}
__device__ __forceinline__ void cpa_wait1() {
    asm volatile("cp.async.wait_group 1;" ::: "memory");
}

// smem layout (bytes): AH | AL | BUF0(BH,BL) | BUF1(BH,BL)
#define TILE_B   (128 * SA * 2)          // 34816
#define OFF_AH   0
#define OFF_AL   (TILE_B)
#define BUF0     (2 * TILE_B)
#define BUF1     (4 * TILE_B)
#define SMEM_MM  (6 * TILE_B)            // 208896
#define SMEM_EDGE (SMEM_MM + 1536)       // + staged src/dst/g

// -------- prep: Wt_hi/Wt_lo[i][n][k] = split(W[i][k][n]) ---------------------
__global__ void prep_w_kernel(const float* __restrict__ W) {
    int t = blockIdx.x * 256 + threadIdx.x;
    if (t >= 9 * D * D) return;
    int i = t >> 14, rem = t & 16383, n = rem >> 7, k = rem & 127;
    float v = W[(i << 14) + (k << 7) + n];
    __nv_bfloat16 h = __float2bfloat16(v);
    S_Wh[t] = h;
    S_Wl[t] = __float2bfloat16(v - __bfloat162float(h));
}

// ---- shared building blocks -------------------------------------------------
__device__ __forceinline__ void prefetch_B(uint32_t sb, uint32_t buf, int idx,
                                           int tid) {
    const int n = tid >> 2, cp4 = tid & 3;
    const __nv_bfloat16* sH = S_Wh + (size_t)idx * 16384 + n * 128 + cp4 * 32;
    const __nv_bfloat16* sL = S_Wl + (size_t)idx * 16384 + n * 128 + cp4 * 32;
    uint32_t dH = sb + buf + (uint32_t)(n * SA + cp4 * 32) * 2;
    uint32_t dL = dH + TILE_B;
#pragma unroll
    for (int j = 0; j < 4; j++) {
        cpa16(dH + j * 16, sH + j * 8);
        cpa16(dL + j * 16, sL + j * 8);
    }
}

__device__ __forceinline__ void split_A(const float* __restrict__ X, char* smem,
                                        int m0, int M, int tid) {
    const int row = tid >> 2, cp = tid & 3;
    const bool valid = (m0 + row) < M;
    const float* xr = X + (size_t)(m0 + row) * D + cp * 32;
    __nv_bfloat16* aH = (__nv_bfloat16*)(smem + OFF_AH) + row * SA + cp * 32;
    __nv_bfloat16* aL = (__nv_bfloat16*)(smem + OFF_AL) + row * SA + cp * 32;
#pragma unroll
    for (int j = 0; j < 8; j++) {
        float4 v = valid ? *(const float4*)(xr + j * 4)
                         : make_float4(0.f, 0.f, 0.f, 0.f);
        __nv_bfloat16 h0 = __float2bfloat16(v.x), h1 = __float2bfloat16(v.y);
        __nv_bfloat16 h2 = __float2bfloat16(v.z), h3 = __float2bfloat16(v.w);
        aH[j * 4 + 0] = h0; aH[j * 4 + 1] = h1;
        aH[j * 4 + 2] = h2; aH[j * 4 + 3] = h3;
        aL[j * 4 + 0] = __float2bfloat16(v.x - __bfloat162float(h0));
        aL[j * 4 + 1] = __float2bfloat16(v.y - __bfloat162float(h1));
        aL[j * 4 + 2] = __float2bfloat16(v.z - __bfloat162float(h2));
        aL[j * 4 + 3] = __float2bfloat16(v.w - __bfloat162float(h3));
    }
}

__device__ __forceinline__ void kloop(uint32_t sb, uint32_t buf,
                                      const uint32_t* aBase,
                                      const uint32_t* bBase,
                                      float c[2][4][4]) {
#pragma unroll
    for (int t = 0; t < 2; t++)
#pragma unroll
        for (int j = 0; j < 4; j++)
#pragma unroll
            for (int q = 0; q < 4; q++) c[t][j][q] = 0.f;
#pragma unroll
    for (int ks = 0; ks < 8; ks++) {
        const uint32_t ko = (uint32_t)(ks * 16) * 2;
        uint32_t ah[2][4], al[2][4];
#pragma unroll
        for (int t = 0; t < 2; t++) {
            ldm_x4(ah[t][0], ah[t][1], ah[t][2], ah[t][3],
                   sb + OFF_AH + aBase[t] + ko);
            ldm_x4(al[t][0], al[t][1], al[t][2], al[t][3],
                   sb + OFF_AL + aBase[t] + ko);
        }
        uint32_t bh[4][2], bl[4][2];
#pragma unroll
        for (int jj = 0; jj < 2; jj++) {
            uint32_t r0, r1, r2, r3;
            ldm_x4(r0, r1, r2, r3, sb + buf + bBase[jj] + ko);
            bh[jj * 2 + 0][0] = r0; bh[jj * 2 + 0][1] = r1;
            bh[jj * 2 + 1][0] = r2; bh[jj * 2 + 1][1] = r3;
            ldm_x4(r0, r1, r2, r3, sb + buf + TILE_B + bBase[jj] + ko);
            bl[jj * 2 + 0][0] = r0; bl[jj * 2 + 0][1] = r1;
            bl[jj * 2 + 1][0] = r2; bl[jj * 2 + 1][1] = r3;
        }
#pragma unroll
        for (int t = 0; t < 2; t++)
#pragma unroll
            for (int j = 0; j < 4; j++) {
                mma16816(c[t][j], ah[t], bh[j]);
                mma16816(c[t][j], ah[t], bl[j]);
                mma16816(c[t][j], al[t], bh[j]);
            }
    }
}

// -------- HMMA GEMM, cp.async double-buffered B, up to 3 fused weights -------
__global__ void __launch_bounds__(512, 1) gemm_mma_kernel(
    const float* __restrict__ X, const float* __restrict__ bias9,
    int i0, int i1, int i2,
    float* __restrict__ Y0, float* __restrict__ Y1, float* __restrict__ Y2,
    int M)
{
    extern __shared__ char smem[];
    const uint32_t sb = smem_u32(smem);
    const int tid  = threadIdx.x;
    const int lane = tid & 31;
    const int warp = tid >> 5;
    const int wm   = warp >> 2;
    const int wn   = warp & 3;
    const int m0   = blockIdx.x * 128;
    const int idxs[3] = {i0, i1, i2};
    float* const outs[3] = {Y0, Y1, Y2};
    const int nW = (i1 < 0) ? 1 : ((i2 < 0) ? 2 : 3);

    prefetch_B(sb, BUF0, idxs[0], tid);
    cpa_commit();
    split_A(X, smem, m0, M, tid);

    const int lt = lane >> 3, lr = lane & 7;
    uint32_t aBase[2];
#pragma unroll
    for (int t = 0; t < 2; t++)
        aBase[t] = (uint32_t)((wm * 32 + t * 16 + (lt & 1) * 8 + lr) * SA
                              + (lt >> 1) * 8) * 2;
    uint32_t bBase[2];
#pragma unroll
    for (int jj = 0; jj < 2; jj++)
        bBase[jj] = (uint32_t)((wn * 32 + jj * 16 + (lt >> 1) * 8 + lr) * SA
                               + (lt & 1) * 8) * 2;

    for (int w = 0; w < nW; w++) {
        if (w + 1 < nW) {
            prefetch_B(sb, (w & 1) ? BUF0 : BUF1, idxs[w + 1], tid);
            cpa_commit();
            cpa_wait1();
        } else {
            cpa_wait0();
        }
        __syncthreads();     // B(w) ready for all threads; A ready (w==0)

        float c[2][4][4];
        kloop(sb, (w & 1) ? BUF1 : BUF0, aBase, bBase, c);

        // epilogue: bias + store
        {
            float* Y = outs[w];
            const float* bv = bias9 + idxs[w] * D;
            const int g = lane >> 2, tg = lane & 3;
#pragma unroll
            for (int t = 0; t < 2; t++) {
                const int r0 = m0 + wm * 32 + t * 16 + g;
                const int r1 = r0 + 8;
#pragma unroll
                for (int j = 0; j < 4; j++) {
                    const int col = wn * 32 + j * 8 + tg * 2;
                    const float2 bb = *(const float2*)(bv + col);
                    if (r0 < M)
                        *(float2*)(Y + (size_t)r0 * D + col) =
                            make_float2(c[t][j][0] + bb.x, c[t][j][1] + bb.y);
                    if (r1 < M)
                        *(float2*)(Y + (size_t)r1 * D + col) =
                            make_float2(c[t][j][2] + bb.x, c[t][j][3] + bb.y);
                }
            }
        }
        __syncthreads();     // all reads of buffer(w) done before it is reused
    }
}

// -------- B(e) GEMM fused with edge_pre: e_pre = B(e)+Ah[src]+Ah[dst]+Cu[g] --
__global__ void __launch_bounds__(512, 1) gemm_edge_kernel(
    const float* __restrict__ X, const float* __restrict__ bias9, int idx,
    float* __restrict__ E1, const float* __restrict__ Ah,
    const float* __restrict__ Cu,
    const int* __restrict__ src, const int* __restrict__ dst,
    const int* __restrict__ a2g, int E)
{
    extern __shared__ char smem[];
    const uint32_t sb = smem_u32(smem);
    int* s_src = (int*)(smem + SMEM_MM);
    int* s_dst = s_src + 128;
    int* s_g   = s_dst + 128;
    const int tid  = threadIdx.x;
    const int lane = tid & 31;
    const int warp = tid >> 5;
    const int wm   = warp >> 2;
    const int wn   = warp & 3;
    const int m0   = blockIdx.x * 128;

    prefetch_B(sb, BUF0, idx, tid);
    cpa_commit();
    if (tid < 128) {
        int e = m0 + tid;
        int s = (e < E) ? src[e] : 0;
        s_src[tid] = s;
        s_dst[tid] = (e < E) ? dst[e] : 0;
        s_g[tid]   = a2g[s];
    }
    split_A(X, smem, m0, E, tid);

    const int lt = lane >> 3, lr = lane & 7;
    uint32_t aBase[2];
#pragma unroll
    for (int t = 0; t < 2; t++)
        aBase[t] = (uint32_t)((wm * 32 + t * 16 + (lt & 1) * 8 + lr) * SA
                              + (lt >> 1) * 8) * 2;
    uint32_t bBase[2];
#pragma unroll
    for (int jj = 0; jj < 2; jj++)
        bBase[jj] = (uint32_t)((wn * 32 + jj * 16 + (lt >> 1) * 8 + lr) * SA
                               + (lt & 1) * 8) * 2;

    cpa_wait0();
    __syncthreads();

    float c[2][4][4];
    kloop(sb, BUF0, aBase, bBase, c);

    // fused epilogue: gathers + write e_pre + BN stats
    const float* bv = bias9 + idx * D;
    const int g = lane >> 2, tg = lane & 3;
    float ssum[8], ssq[8];
#pragma unroll
    for (int i = 0; i < 8; i++) { ssum[i] = 0.f; ssq[i] = 0.f; }

#pragma unroll
    for (int t = 0; t < 2; t++) {
#pragma unroll
        for (int ri = 0; ri < 2; ri++) {
            const int lrow = wm * 32 + t * 16 + g + ri * 8;
            const int row  = m0 + lrow;
            if (row < E) {
                const float* a1 = Ah + (size_t)s_src[lrow] * D;
                const float* a2 = Ah + (size_t)s_dst[lrow] * D;
                const float* cu = Cu + (size_t)s_g[lrow] * D;
#pragma unroll
                for (int j = 0; j < 4; j++) {
                    const int col = wn * 32 + j * 8 + tg * 2;
                    const float2 bb = *(const float2*)(bv + col);
                    const float2 g1 = *(const float2*)(a1 + col);
                    const float2 g2 = *(const float2*)(a2 + col);
                    const float2 g3 = *(const float2*)(cu + col);
                    float vx = c[t][j][ri * 2 + 0] + bb.x + g1.x + g2.x + g3.x;
                    float vy = c[t][j][ri * 2 + 1] + bb.y + g1.y + g2.y + g3.y;
                    *(float2*)(E1 + (size_t)row * D + col) = make_float2(vx, vy);
                    ssum[j * 2 + 0] += vx; ssq[j * 2 + 0] += vx * vx;
                    ssum[j * 2 + 1] += vy; ssq[j * 2 + 1] += vy * vy;
                }
            }
        }
    }
    // reduce over the 8 lanes sharing each column (stride-4 lanes)
#pragma unroll
    for (int i = 0; i < 8; i++) {
        ssum[i] += __shfl_down_sync(0xffffffffu, ssum[i], 16);
        ssq[i]  += __shfl_down_sync(0xffffffffu, ssq[i], 16);
        ssum[i] += __shfl_down_sync(0xffffffffu, ssum[i], 8);
        ssq[i]  += __shfl_down_sync(0xffffffffu, ssq[i], 8);
        ssum[i] += __shfl_down_sync(0xffffffffu, ssum[i], 4);
        ssq[i]  += __shfl_down_sync(0xffffffffu, ssq[i], 4);
    }
    if (lane < 4) {
#pragma unroll
        for (int j = 0; j < 4; j++) {
            const int col = wn * 32 + j * 8 + lane * 2;
            atomicAdd(&S_stats[0 * D + col],     ssum[j * 2 + 0]);
            atomicAdd(&S_stats[0 * D + col + 1], ssum[j * 2 + 1]);
            atomicAdd(&S_stats[1 * D + col],     ssq[j * 2 + 0]);
            atomicAdd(&S_stats[1 * D + col + 1], ssq[j * 2 + 1]);
        }
    }
}

// ======================= non-GEMM stages =====================================
__global__ void e_norm_gate_kernel(const float* __restrict__ E1,
    const float* __restrict__ gamma, const float* __restrict__ beta,
    float* __restrict__ e_out, const float* __restrict__ Eh,
    const int* __restrict__ src, const int* __restrict__ dst,
    int E, float invE)
{
    __shared__ int s_src[EROWS], s_dst[EROWS];
    const int tid = threadIdx.x;
    const int rl  = tid >> 5;
    const int c4  = (tid & 31) * 4;
    const int e0  = blockIdx.x * EROWS;
    if (e0 + tid < E) { s_src[tid] = src[e0 + tid]; s_dst[tid] = dst[e0 + tid]; }
    __syncthreads();
    float gm[4], bt[4];
#pragma unroll
    for (int i = 0; i < 4; i++) {
        int c = c4 + i;
        float mu  = S_stats[c] * invE;
        float var = S_stats[D + c] * invE - mu * mu;
        float rs  = rsqrtf(var + 1e-5f);
        gm[i] = gamma[D + c] * rs;
        bt[i] = beta[D + c] - mu * gm[i];
    }
    const int nr = min(EROWS, E - e0);
    for (int r = rl; r < nr; r += 4) {
        size_t e = (size_t)(e0 + r);
        float4 x = *(const float4*)(E1 + e * D + c4);
        float4 y;
        y.x = fmaxf(fmaf(x.x, gm[0], bt[0]), 0.f);
        y.y = fmaxf(fmaf(x.y, gm[1], bt[1]), 0.f);
        y.z = fmaxf(fmaf(x.z, gm[2], bt[2]), 0.f);
        y.w = fmaxf(fmaf(x.w, gm[3], bt[3]), 0.f);
        *(float4*)(e_out + e * D + c4) = y;
        float4 sg;
        sg.x = 1.f / (1.f + __expf(-y.x));
        sg.y = 1.f / (1.f + __expf(-y.y));
        sg.z = 1.f / (1.f + __expf(-y.z));
        sg.w = 1.f / (1.f + __expf(-y.w));
        float4 ev = *(const float4*)(Eh + (size_t)s_src[r] * D + c4);
        size_t doff = (size_t)s_dst[r] * D + c4;
        red_add_v4(S_num + doff,
                   make_float4(sg.x * ev.x, sg.y * ev.y, sg.z * ev.z, sg.w * ev.w));
        red_add_v4(S_den + doff, sg);
    }
}

__global__ void h_pre_kernel(float* __restrict__ Dh,
    const float* __restrict__ Fu, const int* __restrict__ a2g, int N)
{
    __shared__ int s_g[EROWS];
    const int tid = threadIdx.x;
    const int n0  = blockIdx.x * EROWS;
    if (n0 + tid < N) s_g[tid] = a2g[n0 + tid];
    __syncthreads();
    const int nr = min(EROWS, N - n0);
    float sum = 0.f, sq = 0.f;
    for (int r = 0; r < nr; r++) {
        size_t n = (size_t)(n0 + r);
        float h1 = S_num[n * D + tid] / (S_den[n * D + tid] + 1e-6f);
        float v  = Dh[n * D + tid] + h1 + Fu[(size_t)s_g[r] * D + tid];
        Dh[n * D + tid] = v;
        sum += v; sq += v * v;
    }
    atomicAdd(&S_stats[2 * D + tid], sum);
    atomicAdd(&S_stats[3 * D + tid], sq);
}

__global__ void norm_kernel(const float* __restrict__ Xp,
    const float* __restrict__ gamma, const float* __restrict__ beta,
    float* __restrict__ out, int M, float invM, int statRow, int bnRow)
{
    const int tid = threadIdx.x;
    float mu  = S_stats[statRow * D + tid] * invM;
    float var = S_stats[(statRow + 1) * D + tid] * invM - mu * mu;
    float rs  = rsqrtf(var + 1e-5f);
    float gm  = gamma[bnRow * D + tid] * rs;
    float bt  = beta[bnRow * D + tid] - mu * gm;
    const int n0 = blockIdx.x * EROWS;
    const int nr = min(EROWS, M - n0);
    for (int r = 0; r < nr; r++) {
        size_t n = (size_t)(n0 + r);
        out[n * D + tid] = fmaxf(fmaf(Xp[n * D + tid], gm, bt), 0.f);
    }
}

__global__ void acc_atoms_kernel(const float* __restrict__ Gh,
    const int* __restrict__ a2g, int N)
{
    __shared__ int s_g[EROWS];
    const int tid = threadIdx.x;
    const int n0  = blockIdx.x * EROWS;
    if (n0 + tid < N) s_g[tid] = a2g[n0 + tid];
    __syncthreads();
    const int nr = min(EROWS, N - n0);
    float accv = 0.f;
    int gc = -1;
    for (int r = 0; r < nr; r++) {
        int g = s_g[r];
        if (g != gc) {
            if (gc >= 0) atomicAdd(&S_accG[(size_t)gc * D + tid], accv);
            gc = g; accv = 0.f;
        }
        accv += Gh[(size_t)(n0 + r) * D + tid];
    }
    if (gc >= 0) atomicAdd(&S_accG[(size_t)gc * D + tid], accv);
    if (tid == 0) {
        int gc2 = -1; float c = 0.f;
        for (int r = 0; r < nr; r++) {
            int g = s_g[r];
            if (g != gc2) {
                if (gc2 >= 0) atomicAdd(&S_cnt[gc2], c);
                gc2 = g; c = 0.f;
            }
            c += 1.f;
        }
        if (gc2 >= 0) atomicAdd(&S_cnt[gc2], c);
    }
}

__global__ void acc_edges_kernel(const float* __restrict__ He,
    const int* __restrict__ dst, const int* __restrict__ a2g, int E)
{
    __shared__ int s_g[EROWS];
    const int tid = threadIdx.x;
    const int rl  = tid >> 5;
    const int c4  = (tid & 31) * 4;
    const int e0  = blockIdx.x * EROWS;
    if (e0 + tid < E) s_g[tid] = a2g[dst[e0 + tid]];
    __syncthreads();
    const int nr = min(EROWS, E - e0);
    for (int r = rl; r < nr; r += 4) {
        float4 v = *(const float4*)(He + (size_t)(e0 + r) * D + c4);
        red_add_v4(S_accHe + (size_t)s_g[r] * D + c4, v);
    }
}

__global__ void u_pre_kernel(float* __restrict__ Iu, int G, float invE)
{
    const int tid = threadIdx.x;
    const int g0  = blockIdx.x * EROWS;
    const int nr  = min(EROWS, G - g0);
    float sum = 0.f, sq = 0.f;
    for (int r = 0; r < nr; r++) {
        size_t g = (size_t)(g0 + r);
        float c  = fmaxf(S_cnt[g], 1.f);
        float v  = S_accG[g * D + tid] / c + S_accHe[g * D + tid] * invE
                 + Iu[g * D + tid];
        Iu[g * D + tid] = v;
        sum += v; sq += v * v;
    }
    atomicAdd(&S_stats[4 * D + tid], sum);
    atomicAdd(&S_stats[5 * D + tid], sq);
}

// ---------------------------- launch -----------------------------------------
extern "C" void kernel_launch(void* const* d_in, const int* in_sizes, int n_in,
                              void* d_out, int out_size)
{
    const float* h     = (const float*)d_in[0];
    const float* e     = (const float*)d_in[1];
    const float* u     = (const float*)d_in[2];
    const float* W     = (const float*)d_in[3];
    const float* b     = (const float*)d_in[4];
    const float* gamma = (const float*)d_in[5];
    const float* beta  = (const float*)d_in[6];
    const int*   src   = (const int*)d_in[7];
    const int*   dst   = (const int*)d_in[8];
    const int*   a2g   = (const int*)d_in[9];

    const int N = in_sizes[0] / D;
    const int E = in_sizes[1] / D;
    const int G = in_sizes[2] / D;

    float* out   = (float*)d_out;
    float* h_out = out;
    float* e_out = out + (size_t)N * D;
    float* u_out = out + (size_t)(N + E) * D;

    cudaFuncSetAttribute(gemm_mma_kernel,
                         cudaFuncAttributeMaxDynamicSharedMemorySize, SMEM_MM);
    cudaFuncSetAttribute(gemm_edge_kernel,
                         cudaFuncAttributeMaxDynamicSharedMemorySize, SMEM_EDGE);

    void *pNum, *pDen, *pAccG, *pAccHe, *pCnt, *pStats;
    cudaGetSymbolAddress(&pNum,   S_num);
    cudaGetSymbolAddress(&pDen,   S_den);
    cudaGetSymbolAddress(&pAccG,  S_accG);
    cudaGetSymbolAddress(&pAccHe, S_accHe);
    cudaGetSymbolAddress(&pCnt,   S_cnt);
    cudaGetSymbolAddress(&pStats, S_stats);
    cudaMemsetAsync(pNum,   0, (size_t)N * D * sizeof(float));
    cudaMemsetAsync(pDen,   0, (size_t)N * D * sizeof(float));
    cudaMemsetAsync(pAccG,  0, (size_t)G * D * sizeof(float));
    cudaMemsetAsync(pAccHe, 0, (size_t)G * D * sizeof(float));
    cudaMemsetAsync(pCnt,   0, (size_t)G * sizeof(float));
    cudaMemsetAsync(pStats, 0, 8 * D * sizeof(float));

    float *dAh, *dDh, *dEh, *dE1, *dCu, *dFu, *dIu;
    cudaGetSymbolAddress((void**)&dAh, S_Ah);
    cudaGetSymbolAddress((void**)&dDh, S_Dh);
    cudaGetSymbolAddress((void**)&dEh, S_Eh);
    cudaGetSymbolAddress((void**)&dE1, S_E1);
    cudaGetSymbolAddress((void**)&dCu, S_Cu);
    cudaGetSymbolAddress((void**)&dFu, S_Fu);
    cudaGetSymbolAddress((void**)&dIu, S_Iu);

    const int gN  = (N + 127) / 128;
    const int gE  = (E + 127) / 128;
    const int gG  = (G + 127) / 128;

    // weight prep (transpose + bf16 split)
    prep_w_kernel<<<(9 * D * D + 255) / 256, 256>>>(W);

    // upfront GEMMs (h and u first: edge-fused GEMM gathers from their outputs)
    gemm_mma_kernel<<<gN, 512, SMEM_MM>>>(h, b, 0, 3, 4, dAh, dDh, dEh, N); // A,D,E
    gemm_mma_kernel<<<gG, 512, SMEM_MM>>>(u, b, 2, 5, 8, dCu, dFu, dIu, G); // C,F,I
    // B(e) GEMM fused with edge_pre (writes e_pre + BN stats)
    gemm_edge_kernel<<<gE, 512, SMEM_EDGE>>>(e, b, 1, dE1, dAh, dCu,
                                             src, dst, a2g, E);

    // edge norm + gated scatter
    e_norm_gate_kernel<<<gE, EROWS>>>(dE1, gamma, beta, e_out, dEh, src, dst,
                                      E, 1.f / (float)E);

    // atom update
    h_pre_kernel<<<gN, EROWS>>>(dDh, dFu, a2g, N);
    norm_kernel<<<gN, EROWS>>>(dDh, gamma, beta, h_out, N, 1.f / (float)N, 2, 0);

    // global update
    gemm_mma_kernel<<<gN, 512, SMEM_MM>>>(h_out, b, 6, -1, -1, dAh, 0, 0, N); // G
    gemm_mma_kernel<<<gE, 512, SMEM_MM>>>(e_out, b, 7, -1, -1, dE1, 0, 0, E); // H
    acc_atoms_kernel<<<gN, EROWS>>>(dAh, a2g, N);
    acc_edges_kernel<<<gE, EROWS>>>(dE1, dst, a2g, E);
    u_pre_kernel<<<gG, EROWS>>>(dIu, G, 1.f / (float)E);
    norm_kernel<<<gG, EROWS>>>(dIu, gamma, beta, u_out, G, 1.f / (float)G, 4, 2);
}

// round 11
// speedup vs baseline: 1.0864x; 1.0864x over previous
#include <cuda_runtime.h>
#include <cuda_bf16.h>
#include <math.h>
#include <stdint.h>

#define D      128
#define NMAX   200000
#define EMAX   600000
#define GMAX   10000
#define EROWS  128
#define SA     136          // smem tile stride in bf16 elements

// ---------------- scratch (device globals; no runtime allocation) -----------
__device__ float S_Ah [(size_t)NMAX * D];   // A(h)
__device__ float S_Dh [(size_t)NMAX * D];   // D(h) -> h_pre in place
__device__ float S_Eh [(size_t)NMAX * D];   // E(h)
__device__ float S_num[(size_t)NMAX * D];
__device__ float S_den[(size_t)NMAX * D];
__device__ float S_E1 [(size_t)EMAX * D];   // B(e) -> e_pre
__device__ float S_Cu [(size_t)GMAX * D];
__device__ float S_Fu [(size_t)GMAX * D];
__device__ float S_Iu [(size_t)GMAX * D];
__device__ float S_accG [(size_t)GMAX * D];
__device__ float S_accHe[(size_t)GMAX * D];
__device__ float S_cnt[GMAX];
__device__ float S_stats[8 * D];
// transposed bf16 split weights: [9][n=128][k=128]
__device__ __align__(16) __nv_bfloat16 S_Wh[9 * D * D];
__device__ __align__(16) __nv_bfloat16 S_Wl[9 * D * D];

// ---------------- helpers ----------------------------------------------------
__device__ __forceinline__ uint32_t smem_u32(const void* p) {
    uint32_t a;
    asm("{ .reg .u64 t; cvta.to.shared.u64 t, %1; cvt.u32.u64 %0, t; }"
        : "=r"(a) : "l"(p));
    return a;
}
__device__ __forceinline__ void ldm_x4(uint32_t& r0, uint32_t& r1,
                                       uint32_t& r2, uint32_t& r3, uint32_t a) {
    asm volatile("ldmatrix.sync.aligned.m8n8.x4.shared.b16 {%0,%1,%2,%3}, [%4];"
                 : "=r"(r0), "=r"(r1), "=r"(r2), "=r"(r3) : "r"(a));
}
__device__ __forceinline__ void mma16816(float* c, const uint32_t* a,
                                         const uint32_t* b) {
    asm volatile(
        "mma.sync.aligned.m16n8k16.row.col.f32.bf16.bf16.f32 "
        "{%0,%1,%2,%3}, {%4,%5,%6,%7}, {%8,%9}, {%0,%1,%2,%3};"
        : "+f"(c[0]), "+f"(c[1]), "+f"(c[2]), "+f"(c[3])
        : "r"(a[0]), "r"(a[1]), "r"(a[2]), "r"(a[3]), "r"(b[0]), "r"(b[1]));
}
__device__ __forceinline__ void red_add_v4(float* p, float4 v) {
    asm volatile("red.global.add.v4.f32 [%0], {%1,%2,%3,%4};"
                 :: "l"(p), "f"(v.x), "f"(v.y), "f"(v.z), "f"(v.w) : "memory");
}
__device__ __forceinline__ void cpa16(uint32_t dst, const void* src) {
    asm volatile("cp.async.cg.shared.global [%0], [%1], 16;"
                 :: "r"(dst), "l"(src) : "memory");
}
__device__ __forceinline__ void cpa_commit() {
    asm volatile("cp.async.commit_group;" ::: "memory");
}
__device__ __forceinline__ void cpa_wait0() {
    asm volatile("cp.async.wait_group 0;" ::: "memory");
}
__device__ __forceinline__ void cpa_wait1() {
    asm volatile("cp.async.wait_group 1;" ::: "memory");
}

// smem layout (bytes): AH | AL | BUF0(BH,BL) | BUF1(BH,BL)
#define TILE_B    (128 * SA * 2)         // 34816
#define OFF_AH    0
#define OFF_AL    (TILE_B)
#define BUF0      (2 * TILE_B)
#define BUF1      (4 * TILE_B)
#define SMEM_MM   (6 * TILE_B)           // 208896
#define SMEM_ACC  (4 * TILE_B + 512)     // A + 1 B buffer + s_g[128]

// -------- prep: Wt_hi/Wt_lo[i][n][k] = split(W[i][k][n]) ---------------------
__global__ void prep_w_kernel(const float* __restrict__ W) {
    int t = blockIdx.x * 256 + threadIdx.x;
    if (t >= 9 * D * D) return;
    int i = t >> 14, rem = t & 16383, n = rem >> 7, k = rem & 127;
    float v = W[(i << 14) + (k << 7) + n];
    __nv_bfloat16 h = __float2bfloat16(v);
    S_Wh[t] = h;
    S_Wl[t] = __float2bfloat16(v - __bfloat162float(h));
}

// ---- shared building blocks -------------------------------------------------
__device__ __forceinline__ void prefetch_B(uint32_t sb, uint32_t buf, int idx,
                                           int tid) {
    const int n = tid >> 2, cp4 = tid & 3;
    const __nv_bfloat16* sH = S_Wh + (size_t)idx * 16384 + n * 128 + cp4 * 32;
    const __nv_bfloat16* sL = S_Wl + (size_t)idx * 16384 + n * 128 + cp4 * 32;
    uint32_t dH = sb + buf + (uint32_t)(n * SA + cp4 * 32) * 2;
    uint32_t dL = dH + TILE_B;
#pragma unroll
    for (int j = 0; j < 4; j++) {
        cpa16(dH + j * 16, sH + j * 8);
        cpa16(dL + j * 16, sL + j * 8);
    }
}

__device__ __forceinline__ void split_A(const float* __restrict__ X, char* smem,
                                        int m0, int M, int tid) {
    const int row = tid >> 2, cp = tid & 3;
    const bool valid = (m0 + row) < M;
    const float* xr = X + (size_t)(m0 + row) * D + cp * 32;
    __nv_bfloat16* aH = (__nv_bfloat16*)(smem + OFF_AH) + row * SA + cp * 32;
    __nv_bfloat16* aL = (__nv_bfloat16*)(smem + OFF_AL) + row * SA + cp * 32;
#pragma unroll
    for (int j = 0; j < 8; j++) {
        float4 v = valid ? *(const float4*)(xr + j * 4)
                         : make_float4(0.f, 0.f, 0.f, 0.f);
        __nv_bfloat16 h0 = __float2bfloat16(v.x), h1 = __float2bfloat16(v.y);
        __nv_bfloat16 h2 = __float2bfloat16(v.z), h3 = __float2bfloat16(v.w);
        aH[j * 4 + 0] = h0; aH[j * 4 + 1] = h1;
        aH[j * 4 + 2] = h2; aH[j * 4 + 3] = h3;
        aL[j * 4 + 0] = __float2bfloat16(v.x - __bfloat162float(h0));
        aL[j * 4 + 1] = __float2bfloat16(v.y - __bfloat162float(h1));
        aL[j * 4 + 2] = __float2bfloat16(v.z - __bfloat162float(h2));
        aL[j * 4 + 3] = __float2bfloat16(v.w - __bfloat162float(h3));
    }
}

__device__ __forceinline__ void kloop(uint32_t sb, uint32_t buf,
                                      const uint32_t* aBase,
                                      const uint32_t* bBase,
                                      float c[2][4][4]) {
#pragma unroll
    for (int t = 0; t < 2; t++)
#pragma unroll
        for (int j = 0; j < 4; j++)
#pragma unroll
            for (int q = 0; q < 4; q++) c[t][j][q] = 0.f;
#pragma unroll
    for (int ks = 0; ks < 8; ks++) {
        const uint32_t ko = (uint32_t)(ks * 16) * 2;
        uint32_t ah[2][4], al[2][4];
#pragma unroll
        for (int t = 0; t < 2; t++) {
            ldm_x4(ah[t][0], ah[t][1], ah[t][2], ah[t][3],
                   sb + OFF_AH + aBase[t] + ko);
            ldm_x4(al[t][0], al[t][1], al[t][2], al[t][3],
                   sb + OFF_AL + aBase[t] + ko);
        }
        uint32_t bh[4][2], bl[4][2];
#pragma unroll
        for (int jj = 0; jj < 2; jj++) {
            uint32_t r0, r1, r2, r3;
            ldm_x4(r0, r1, r2, r3, sb + buf + bBase[jj] + ko);
            bh[jj * 2 + 0][0] = r0; bh[jj * 2 + 0][1] = r1;
            bh[jj * 2 + 1][0] = r2; bh[jj * 2 + 1][1] = r3;
            ldm_x4(r0, r1, r2, r3, sb + buf + TILE_B + bBase[jj] + ko);
            bl[jj * 2 + 0][0] = r0; bl[jj * 2 + 0][1] = r1;
            bl[jj * 2 + 1][0] = r2; bl[jj * 2 + 1][1] = r3;
        }
#pragma unroll
        for (int t = 0; t < 2; t++)
#pragma unroll
            for (int j = 0; j < 4; j++) {
                mma16816(c[t][j], ah[t], bh[j]);
                mma16816(c[t][j], ah[t], bl[j]);
                mma16816(c[t][j], al[t], bh[j]);
            }
    }
}

// -------- HMMA GEMM, cp.async double-buffered B, up to 3 fused weights -------
__global__ void __launch_bounds__(512, 1) gemm_mma_kernel(
    const float* __restrict__ X, const float* __restrict__ bias9,
    int i0, int i1, int i2,
    float* __restrict__ Y0, float* __restrict__ Y1, float* __restrict__ Y2,
    int M)
{
    extern __shared__ char smem[];
    const uint32_t sb = smem_u32(smem);
    const int tid  = threadIdx.x;
    const int lane = tid & 31;
    const int warp = tid >> 5;
    const int wm   = warp >> 2;
    const int wn   = warp & 3;
    const int m0   = blockIdx.x * 128;
    const int idxs[3] = {i0, i1, i2};
    float* const outs[3] = {Y0, Y1, Y2};
    const int nW = (i1 < 0) ? 1 : ((i2 < 0) ? 2 : 3);

    prefetch_B(sb, BUF0, idxs[0], tid);
    cpa_commit();
    split_A(X, smem, m0, M, tid);

    const int lt = lane >> 3, lr = lane & 7;
    uint32_t aBase[2];
#pragma unroll
    for (int t = 0; t < 2; t++)
        aBase[t] = (uint32_t)((wm * 32 + t * 16 + (lt & 1) * 8 + lr) * SA
                              + (lt >> 1) * 8) * 2;
    uint32_t bBase[2];
#pragma unroll
    for (int jj = 0; jj < 2; jj++)
        bBase[jj] = (uint32_t)((wn * 32 + jj * 16 + (lt >> 1) * 8 + lr) * SA
                               + (lt & 1) * 8) * 2;

    for (int w = 0; w < nW; w++) {
        if (w + 1 < nW) {
            prefetch_B(sb, (w & 1) ? BUF0 : BUF1, idxs[w + 1], tid);
            cpa_commit();
            cpa_wait1();
        } else {
            cpa_wait0();
        }
        __syncthreads();

        float c[2][4][4];
        kloop(sb, (w & 1) ? BUF1 : BUF0, aBase, bBase, c);

        {
            float* Y = outs[w];
            const float* bv = bias9 + idxs[w] * D;
            const int g = lane >> 2, tg = lane & 3;
#pragma unroll
            for (int t = 0; t < 2; t++) {
                const int r0 = m0 + wm * 32 + t * 16 + g;
                const int r1 = r0 + 8;
#pragma unroll
                for (int j = 0; j < 4; j++) {
                    const int col = wn * 32 + j * 8 + tg * 2;
                    const float2 bb = *(const float2*)(bv + col);
                    if (r0 < M)
                        *(float2*)(Y + (size_t)r0 * D + col) =
                            make_float2(c[t][j][0] + bb.x, c[t][j][1] + bb.y);
                    if (r1 < M)
                        *(float2*)(Y + (size_t)r1 * D + col) =
                            make_float2(c[t][j][2] + bb.x, c[t][j][3] + bb.y);
                }
            }
        }
        __syncthreads();
    }
}

// -------- HMMA GEMM with segment-sum epilogue (REDG scatter, no store) -------
// acc[g][:] += X[row]@W + b  where g = a2g[map1 ? map1[row] : row]
__global__ void __launch_bounds__(512, 1) gemm_acc_kernel(
    const float* __restrict__ X, const float* __restrict__ bias9, int idx,
    float* __restrict__ acc, const int* __restrict__ map1,
    const int* __restrict__ a2g, int M)
{
    extern __shared__ char smem[];
    const uint32_t sb = smem_u32(smem);
    int* s_g = (int*)(smem + 4 * TILE_B);
    const int tid  = threadIdx.x;
    const int lane = tid & 31;
    const int warp = tid >> 5;
    const int wm   = warp >> 2;
    const int wn   = warp & 3;
    const int m0   = blockIdx.x * 128;

    prefetch_B(sb, BUF0, idx, tid);
    cpa_commit();
    if (tid < 128) {
        int row = m0 + tid;
        int r = (row < M) ? (map1 ? map1[row] : row) : 0;
        s_g[tid] = (row < M) ? a2g[r] : 0;
    }
    split_A(X, smem, m0, M, tid);

    const int lt = lane >> 3, lr = lane & 7;
    uint32_t aBase[2];
#pragma unroll
    for (int t = 0; t < 2; t++)
        aBase[t] = (uint32_t)((wm * 32 + t * 16 + (lt & 1) * 8 + lr) * SA
                              + (lt >> 1) * 8) * 2;
    uint32_t bBase[2];
#pragma unroll
    for (int jj = 0; jj < 2; jj++)
        bBase[jj] = (uint32_t)((wn * 32 + jj * 16 + (lt >> 1) * 8 + lr) * SA
                               + (lt & 1) * 8) * 2;

    cpa_wait0();
    __syncthreads();

    float c[2][4][4];
    kloop(sb, BUF0, aBase, bBase, c);

    // epilogue: pair lanes (tg,tg^1) into 16B quads, REDG into acc[g]
    const float* bv = bias9 + idx * D;
    const int g = lane >> 2, tg = lane & 3;
#pragma unroll
    for (int t = 0; t < 2; t++) {
#pragma unroll
        for (int ri = 0; ri < 2; ri++) {
            const int lrow = wm * 32 + t * 16 + g + ri * 8;
            const int row  = m0 + lrow;
            const bool valid = row < M;
            float* ap = acc + (size_t)s_g[lrow] * D;
#pragma unroll
            for (int j = 0; j < 4; j++) {
                const int col = wn * 32 + j * 8 + tg * 2;
                const float2 bb = *(const float2*)(bv + col);
                float vx = c[t][j][ri * 2 + 0] + bb.x;
                float vy = c[t][j][ri * 2 + 1] + bb.y;
                float ox = __shfl_xor_sync(0xffffffffu, vx, 1);
                float oy = __shfl_xor_sync(0xffffffffu, vy, 1);
                if (valid && (tg & 1) == 0)
                    red_add_v4(ap + col, make_float4(vx, vy, ox, oy));
            }
        }
    }
}

// ======================= non-GEMM stages =====================================
__global__ void edge_pre_kernel(const float* __restrict__ Ah,
    float* __restrict__ E1, const float* __restrict__ Cu,
    const int* __restrict__ src, const int* __restrict__ dst,
    const int* __restrict__ a2g, int E)
{
    __shared__ int s_src[EROWS], s_dst[EROWS], s_g[EROWS];
    const int tid = threadIdx.x;
    const int e0  = blockIdx.x * EROWS;
    if (e0 + tid < E) {
        int s = src[e0 + tid];
        s_src[tid] = s;
        s_dst[tid] = dst[e0 + tid];
        s_g[tid]   = a2g[s];
    }
    __syncthreads();
    const int nr = min(EROWS, E - e0);
    float sum = 0.f, sq = 0.f;
    for (int r = 0; r < nr; r++) {
        size_t e = (size_t)(e0 + r);
        float v = E1[e * D + tid]
                + Ah[(size_t)s_src[r] * D + tid]
                + Ah[(size_t)s_dst[r] * D + tid]
                + Cu[(size_t)s_g[r] * D + tid];
        E1[e * D + tid] = v;
        sum += v; sq += v * v;
    }
    atomicAdd(&S_stats[0 * D + tid], sum);
    atomicAdd(&S_stats[1 * D + tid], sq);
}

__global__ void e_norm_gate_kernel(const float* __restrict__ E1,
    const float* __restrict__ gamma, const float* __restrict__ beta,
    float* __restrict__ e_out, const float* __restrict__ Eh,
    const int* __restrict__ src, const int* __restrict__ dst,
    int E, float invE)
{
    __shared__ int s_src[EROWS], s_dst[EROWS];
    const int tid = threadIdx.x;
    const int rl  = tid >> 5;
    const int c4  = (tid & 31) * 4;
    const int e0  = blockIdx.x * EROWS;
    if (e0 + tid < E) { s_src[tid] = src[e0 + tid]; s_dst[tid] = dst[e0 + tid]; }
    __syncthreads();
    float gm[4], bt[4];
#pragma unroll
    for (int i = 0; i < 4; i++) {
        int c = c4 + i;
        float mu  = S_stats[c] * invE;
        float var = S_stats[D + c] * invE - mu * mu;
        float rs  = rsqrtf(var + 1e-5f);
        gm[i] = gamma[D + c] * rs;
        bt[i] = beta[D + c] - mu * gm[i];
    }
    const int nr = min(EROWS, E - e0);
    for (int r = rl; r < nr; r += 4) {
        size_t e = (size_t)(e0 + r);
        float4 x = *(const float4*)(E1 + e * D + c4);
        float4 y;
        y.x = fmaxf(fmaf(x.x, gm[0], bt[0]), 0.f);
        y.y = fmaxf(fmaf(x.y, gm[1], bt[1]), 0.f);
        y.z = fmaxf(fmaf(x.z, gm[2], bt[2]), 0.f);
        y.w = fmaxf(fmaf(x.w, gm[3], bt[3]), 0.f);
        *(float4*)(e_out + e * D + c4) = y;
        float4 sg;
        sg.x = 1.f / (1.f + __expf(-y.x));
        sg.y = 1.f / (1.f + __expf(-y.y));
        sg.z = 1.f / (1.f + __expf(-y.z));
        sg.w = 1.f / (1.f + __expf(-y.w));
        float4 ev = *(const float4*)(Eh + (size_t)s_src[r] * D + c4);
        size_t doff = (size_t)s_dst[r] * D + c4;
        red_add_v4(S_num + doff,
                   make_float4(sg.x * ev.x, sg.y * ev.y, sg.z * ev.z, sg.w * ev.w));
        red_add_v4(S_den + doff, sg);
    }
}

// h_pre + per-graph atom count (run-length on sorted a2g)
__global__ void h_pre_kernel(float* __restrict__ Dh,
    const float* __restrict__ Fu, const int* __restrict__ a2g, int N)
{
    __shared__ int s_g[EROWS];
    const int tid = threadIdx.x;
    const int n0  = blockIdx.x * EROWS;
    if (n0 + tid < N) s_g[tid] = a2g[n0 + tid];
    __syncthreads();
    const int nr = min(EROWS, N - n0);
    float sum = 0.f, sq = 0.f;
    for (int r = 0; r < nr; r++) {
        size_t n = (size_t)(n0 + r);
        float h1 = S_num[n * D + tid] / (S_den[n * D + tid] + 1e-6f);
        float v  = Dh[n * D + tid] + h1 + Fu[(size_t)s_g[r] * D + tid];
        Dh[n * D + tid] = v;
        sum += v; sq += v * v;
    }
    atomicAdd(&S_stats[2 * D + tid], sum);
    atomicAdd(&S_stats[3 * D + tid], sq);
    if (tid == 0) {
        int gc = -1; float c = 0.f;
        for (int r = 0; r < nr; r++) {
            int g = s_g[r];
            if (g != gc) {
                if (gc >= 0) atomicAdd(&S_cnt[gc], c);
                gc = g; c = 0.f;
            }
            c += 1.f;
        }
        if (gc >= 0) atomicAdd(&S_cnt[gc], c);
    }
}

__global__ void norm_kernel(const float* __restrict__ Xp,
    const float* __restrict__ gamma, const float* __restrict__ beta,
    float* __restrict__ out, int M, float invM, int statRow, int bnRow)
{
    const int tid = threadIdx.x;
    float mu  = S_stats[statRow * D + tid] * invM;
    float var = S_stats[(statRow + 1) * D + tid] * invM - mu * mu;
    float rs  = rsqrtf(var + 1e-5f);
    float gm  = gamma[bnRow * D + tid] * rs;
    float bt  = beta[bnRow * D + tid] - mu * gm;
    const int n0 = blockIdx.x * EROWS;
    const int nr = min(EROWS, M - n0);
    for (int r = 0; r < nr; r++) {
        size_t n = (size_t)(n0 + r);
        out[n * D + tid] = fmaxf(fmaf(Xp[n * D + tid], gm, bt), 0.f);
    }
}

__global__ void u_pre_kernel(float* __restrict__ Iu, int G, float invE)
{
    const int tid = threadIdx.x;
    const int g0  = blockIdx.x * EROWS;
    const int nr  = min(EROWS, G - g0);
    float sum = 0.f, sq = 0.f;
    for (int r = 0; r < nr; r++) {
        size_t g = (size_t)(g0 + r);
        float c  = fmaxf(S_cnt[g], 1.f);
        float v  = S_accG[g * D + tid] / c + S_accHe[g * D + tid] * invE
                 + Iu[g * D + tid];
        Iu[g * D + tid] = v;
        sum += v; sq += v * v;
    }
    atomicAdd(&S_stats[4 * D + tid], sum);
    atomicAdd(&S_stats[5 * D + tid], sq);
}

// ---------------------------- launch -----------------------------------------
extern "C" void kernel_launch(void* const* d_in, const int* in_sizes, int n_in,
                              void* d_out, int out_size)
{
    const float* h     = (const float*)d_in[0];
    const float* e     = (const float*)d_in[1];
    const float* u     = (const float*)d_in[2];
    const float* W     = (const float*)d_in[3];
    const float* b     = (const float*)d_in[4];
    const float* gamma = (const float*)d_in[5];
    const float* beta  = (const float*)d_in[6];
    const int*   src   = (const int*)d_in[7];
    const int*   dst   = (const int*)d_in[8];
    const int*   a2g   = (const int*)d_in[9];

    const int N = in_sizes[0] / D;
    const int E = in_sizes[1] / D;
    const int G = in_sizes[2] / D;

    float* out   = (float*)d_out;
    float* h_out = out;
    float* e_out = out + (size_t)N * D;
    float* u_out = out + (size_t)(N + E) * D;

    cudaFuncSetAttribute(gemm_mma_kernel,
                         cudaFuncAttributeMaxDynamicSharedMemorySize, SMEM_MM);
    cudaFuncSetAttribute(gemm_acc_kernel,
                         cudaFuncAttributeMaxDynamicSharedMemorySize, SMEM_ACC);

    void *pNum, *pDen, *pAccG, *pAccHe, *pCnt, *pStats;
    cudaGetSymbolAddress(&pNum,   S_num);
    cudaGetSymbolAddress(&pDen,   S_den);
    cudaGetSymbolAddress(&pAccG,  S_accG);
    cudaGetSymbolAddress(&pAccHe, S_accHe);
    cudaGetSymbolAddress(&pCnt,   S_cnt);
    cudaGetSymbolAddress(&pStats, S_stats);
    cudaMemsetAsync(pNum,   0, (size_t)N * D * sizeof(float));
    cudaMemsetAsync(pDen,   0, (size_t)N * D * sizeof(float));
    cudaMemsetAsync(pAccG,  0, (size_t)G * D * sizeof(float));
    cudaMemsetAsync(pAccHe, 0, (size_t)G * D * sizeof(float));
    cudaMemsetAsync(pCnt,   0, (size_t)G * sizeof(float));
    cudaMemsetAsync(pStats, 0, 8 * D * sizeof(float));

    float *dAh, *dDh, *dEh, *dE1, *dCu, *dFu, *dIu, *dAccG, *dAccHe;
    cudaGetSymbolAddress((void**)&dAh, S_Ah);
    cudaGetSymbolAddress((void**)&dDh, S_Dh);
    cudaGetSymbolAddress((void**)&dEh, S_Eh);
    cudaGetSymbolAddress((void**)&dE1, S_E1);
    cudaGetSymbolAddress((void**)&dCu, S_Cu);
    cudaGetSymbolAddress((void**)&dFu, S_Fu);
    cudaGetSymbolAddress((void**)&dIu, S_Iu);
    dAccG  = (float*)pAccG;
    dAccHe = (float*)pAccHe;

    const int gN  = (N + 127) / 128;
    const int gE  = (E + 127) / 128;
    const int gG  = (G + 127) / 128;

    // weight prep (transpose + bf16 split)
    prep_w_kernel<<<(9 * D * D + 255) / 256, 256>>>(W);

    // upfront GEMMs on tensor cores (fused per input)
    gemm_mma_kernel<<<gN, 512, SMEM_MM>>>(h, b, 0, 3, 4, dAh, dDh, dEh, N); // A,D,E
    gemm_mma_kernel<<<gG, 512, SMEM_MM>>>(u, b, 2, 5, 8, dCu, dFu, dIu, G); // C,F,I
    gemm_mma_kernel<<<gE, 512, SMEM_MM>>>(e, b, 1, -1, -1, dE1, 0, 0, E);   // B(e)

    // edge update
    edge_pre_kernel<<<gE, EROWS>>>(dAh, dE1, dCu, src, dst, a2g, E);
    e_norm_gate_kernel<<<gE, EROWS>>>(dE1, gamma, beta, e_out, dEh, src, dst,
                                      E, 1.f / (float)E);

    // atom update (h_pre also accumulates per-graph atom counts)
    h_pre_kernel<<<gN, EROWS>>>(dDh, dFu, a2g, N);
    norm_kernel<<<gN, EROWS>>>(dDh, gamma, beta, h_out, N, 1.f / (float)N, 2, 0);

    // global update: GEMMs with fused segment-sum scatter (no dense output)
    gemm_acc_kernel<<<gN, 512, SMEM_ACC>>>(h_out, b, 6, dAccG, (const int*)0,
                                           a2g, N);                 // G(h_new)
    gemm_acc_kernel<<<gE, 512, SMEM_ACC>>>(e_out, b, 7, dAccHe, dst,
                                           a2g, E);                 // H(e_new)
    u_pre_kernel<<<gG, EROWS>>>(dIu, G, 1.f / (float)E);
    norm_kernel<<<gG, EROWS>>>(dIu, gamma, beta, u_out, G, 1.f / (float)G, 4, 2);
}